// round 2
// baseline (speedup 1.0000x reference)
#include <cuda_runtime.h>
#include <math.h>

#define B_ 8
#define L_ 4096
#define D_ 1024
#define M_ (B_ * L_)      // 32768
#define K_ D_             // 1024

// GEMM tiling
#define BM 128
#define BN 64
#define BK 16
#define TM 8
#define TN 4
#define NT 256
#define NKT (K_ / BK)     // 64

// scan segmentation
#define NSEG 32
#define TSEG (L_ / NSEG)  // 128

// scratch (device globals: allocation inside kernel_launch is forbidden)
__device__ float g_a[(size_t)M_ * D_];            // gate a_t = g_t            (128 MB)
__device__ float g_b[(size_t)M_ * D_];            // b_t = (1-g_t)*c_t         (128 MB)
__device__ float g_sA[B_ * NSEG * D_];            // per-segment A
__device__ float g_sB[B_ * NSEG * D_];            // per-segment B
__device__ float g_pA[B_ * NSEG * D_];            // exclusive prefix A
__device__ float g_pB[B_ * NSEG * D_];            // exclusive prefix B

// ---------------------------------------------------------------------------
// Fused dual GEMM + activations:
//   G = x @ Wg^T + bg ; H = x @ Wh^T + bh
//   a = sigmoid(G) ; b = (1-a) * tanh(H)
// x: (M, K) row-major, Wg/Wh: (N, K) row-major (einsum 'bld,ed')
// ---------------------------------------------------------------------------
__global__ __launch_bounds__(NT, 2)
void gemm_act(const float* __restrict__ x,
              const float* __restrict__ Wg,
              const float* __restrict__ bg,
              const float* __restrict__ Wh,
              const float* __restrict__ bh)
{
    __shared__ float As[2][BK][BM + 4];   // +4 pad: store conflicts 4-way -> 2-way
    __shared__ float Gs[2][BK][BN];       // unpadded: rows 16B aligned for LDS.128
    __shared__ float Hs[2][BK][BN];

    const int tid = threadIdx.x;
    const int m0 = blockIdx.y * BM;
    const int n0 = blockIdx.x * BN;

    // loader mapping: 256 threads, float4 each
    const int lrow = tid >> 2;            // 0..63
    const int lcol = (tid & 3) << 2;      // 0,4,8,12

    const float* xg0 = x  + (size_t)(m0 + lrow)      * K_ + lcol;
    const float* xg1 = x  + (size_t)(m0 + lrow + 64) * K_ + lcol;
    const float* wgp = Wg + (size_t)(n0 + lrow)      * K_ + lcol;
    const float* whp = Wh + (size_t)(n0 + lrow)      * K_ + lcol;

    // compute mapping: 16x16 threads, each TM x TN per output matrix
    const int tm0 = (tid >> 4) * TM;      // 0..120
    const int tn0 = (tid & 15) * TN;      // 0..60

    float accG[TM][TN];
    float accH[TM][TN];
    #pragma unroll
    for (int i = 0; i < TM; ++i)
        #pragma unroll
        for (int j = 0; j < TN; ++j) { accG[i][j] = 0.f; accH[i][j] = 0.f; }

    float4 rx0, rx1, rg, rh;

    // prologue: load + store tile 0
    rx0 = *(const float4*)(xg0);
    rx1 = *(const float4*)(xg1);
    rg  = *(const float4*)(wgp);
    rh  = *(const float4*)(whp);

    As[0][lcol + 0][lrow] = rx0.x;  As[0][lcol + 1][lrow] = rx0.y;
    As[0][lcol + 2][lrow] = rx0.z;  As[0][lcol + 3][lrow] = rx0.w;
    As[0][lcol + 0][lrow + 64] = rx1.x;  As[0][lcol + 1][lrow + 64] = rx1.y;
    As[0][lcol + 2][lrow + 64] = rx1.z;  As[0][lcol + 3][lrow + 64] = rx1.w;
    Gs[0][lcol + 0][lrow] = rg.x;   Gs[0][lcol + 1][lrow] = rg.y;
    Gs[0][lcol + 2][lrow] = rg.z;   Gs[0][lcol + 3][lrow] = rg.w;
    Hs[0][lcol + 0][lrow] = rh.x;   Hs[0][lcol + 1][lrow] = rh.y;
    Hs[0][lcol + 2][lrow] = rh.z;   Hs[0][lcol + 3][lrow] = rh.w;
    __syncthreads();

    for (int kt = 0; kt < NKT; ++kt) {
        const int buf = kt & 1;
        if (kt + 1 < NKT) {
            const int koff = (kt + 1) * BK;
            rx0 = *(const float4*)(xg0 + koff);
            rx1 = *(const float4*)(xg1 + koff);
            rg  = *(const float4*)(wgp + koff);
            rh  = *(const float4*)(whp + koff);
        }

        #pragma unroll
        for (int kk = 0; kk < BK; ++kk) {
            float af[TM], gf[TN], hf[TN];
            #pragma unroll
            for (int i = 0; i < TM; ++i) af[i] = As[buf][kk][tm0 + i];
            #pragma unroll
            for (int j = 0; j < TN; ++j) gf[j] = Gs[buf][kk][tn0 + j];
            #pragma unroll
            for (int j = 0; j < TN; ++j) hf[j] = Hs[buf][kk][tn0 + j];
            #pragma unroll
            for (int i = 0; i < TM; ++i)
                #pragma unroll
                for (int j = 0; j < TN; ++j) {
                    accG[i][j] = fmaf(af[i], gf[j], accG[i][j]);
                    accH[i][j] = fmaf(af[i], hf[j], accH[i][j]);
                }
        }

        if (kt + 1 < NKT) {
            const int nb = buf ^ 1;
            As[nb][lcol + 0][lrow] = rx0.x;  As[nb][lcol + 1][lrow] = rx0.y;
            As[nb][lcol + 2][lrow] = rx0.z;  As[nb][lcol + 3][lrow] = rx0.w;
            As[nb][lcol + 0][lrow + 64] = rx1.x;  As[nb][lcol + 1][lrow + 64] = rx1.y;
            As[nb][lcol + 2][lrow + 64] = rx1.z;  As[nb][lcol + 3][lrow + 64] = rx1.w;
            Gs[nb][lcol + 0][lrow] = rg.x;   Gs[nb][lcol + 1][lrow] = rg.y;
            Gs[nb][lcol + 2][lrow] = rg.z;   Gs[nb][lcol + 3][lrow] = rg.w;
            Hs[nb][lcol + 0][lrow] = rh.x;   Hs[nb][lcol + 1][lrow] = rh.y;
            Hs[nb][lcol + 2][lrow] = rh.z;   Hs[nb][lcol + 3][lrow] = rh.w;
            __syncthreads();
        }
    }

    // epilogue: bias + activations, write a and b
    float bgv[TN], bhv[TN];
    #pragma unroll
    for (int j = 0; j < TN; ++j) {
        bgv[j] = bg[n0 + tn0 + j];
        bhv[j] = bh[n0 + tn0 + j];
    }

    #pragma unroll
    for (int i = 0; i < TM; ++i) {
        float4 av, bv;
        float* avp = (float*)&av;
        float* bvp = (float*)&bv;
        #pragma unroll
        for (int j = 0; j < TN; ++j) {
            const float G = accG[i][j] + bgv[j];
            const float H = accH[i][j] + bhv[j];
            const float a = 1.0f / (1.0f + __expf(-G));
            const float c = tanhf(H);
            avp[j] = a;
            bvp[j] = (1.0f - a) * c;
        }
        const size_t o = (size_t)(m0 + tm0 + i) * D_ + (n0 + tn0);
        *(float4*)(g_a + o) = av;
        *(float4*)(g_b + o) = bv;
    }
}

// ---------------------------------------------------------------------------
// Scan pass 1: per-segment affine reduction (A = prod a, B = fold)
// grid (D/256, NSEG, B) x 256
// ---------------------------------------------------------------------------
__global__ void scan_seg()
{
    const int d = blockIdx.x * blockDim.x + threadIdx.x;
    const int s = blockIdx.y;
    const int b = blockIdx.z;

    size_t base = ((size_t)(b * L_ + s * TSEG)) * D_ + d;
    float A = 1.f, Bv = 0.f;
    #pragma unroll 8
    for (int t = 0; t < TSEG; ++t) {
        const float a  = g_a[base];
        const float bb = g_b[base];
        Bv = fmaf(a, Bv, bb);
        A  = A * a;
        base += D_;
    }
    const size_t o = ((size_t)(b * NSEG + s)) * D_ + d;
    g_sA[o] = A;
    g_sB[o] = Bv;
}

// ---------------------------------------------------------------------------
// Scan pass 2: exclusive prefix over the 32 segments per (b,d) channel
// ---------------------------------------------------------------------------
__global__ void scan_prefix()
{
    const int idx = blockIdx.x * blockDim.x + threadIdx.x;   // 0..8191
    const int b = idx >> 10;          // / D_
    const int d = idx & (D_ - 1);

    float PA = 1.f, PB = 0.f;
    #pragma unroll
    for (int s = 0; s < NSEG; ++s) {
        const size_t o = ((size_t)(b * NSEG + s)) * D_ + d;
        g_pA[o] = PA;
        g_pB[o] = PB;
        const float A  = g_sA[o];
        const float Bs = g_sB[o];
        PB = fmaf(A, PB, Bs);
        PA = PA * A;
    }
}

// ---------------------------------------------------------------------------
// Scan pass 3: apply prefix, recompute segment, write h_t
// ---------------------------------------------------------------------------
__global__ void scan_apply(const float* __restrict__ hidden,
                           float* __restrict__ out)
{
    const int d = blockIdx.x * blockDim.x + threadIdx.x;
    const int s = blockIdx.y;
    const int b = blockIdx.z;

    const size_t po = ((size_t)(b * NSEG + s)) * D_ + d;
    float h = fmaf(g_pA[po], hidden[(size_t)b * D_ + d], g_pB[po]);

    size_t base = ((size_t)(b * L_ + s * TSEG)) * D_ + d;
    #pragma unroll 8
    for (int t = 0; t < TSEG; ++t) {
        const float a  = g_a[base];
        const float bb = g_b[base];
        h = fmaf(a, h, bb);
        out[base] = h;
        base += D_;
    }
}

// ---------------------------------------------------------------------------
extern "C" void kernel_launch(void* const* d_in, const int* in_sizes, int n_in,
                              void* d_out, int out_size)
{
    const float* x      = (const float*)d_in[0];
    const float* hidden = (const float*)d_in[1];
    const float* Wg     = (const float*)d_in[2];
    const float* bg     = (const float*)d_in[3];
    const float* Wh     = (const float*)d_in[4];
    const float* bh     = (const float*)d_in[5];
    float* out = (float*)d_out;

    dim3 gemm_grid(D_ / BN, M_ / BM);          // (16, 256): x-major keeps same-M tiles in-wave for L2
    gemm_act<<<gemm_grid, NT>>>(x, Wg, bg, Wh, bh);

    dim3 scan_grid(D_ / 256, NSEG, B_);        // (4, 32, 8)
    scan_seg<<<scan_grid, 256>>>();
    scan_prefix<<<(B_ * D_) / 256, 256>>>();
    scan_apply<<<scan_grid, 256>>>(hidden, out);
}

// round 7
// speedup vs baseline: 2.3816x; 2.3816x over previous
#include <cuda_runtime.h>
#include <cuda_bf16.h>
#include <math.h>
#include <stdint.h>

#define B_ 8
#define L_ 4096
#define D_ 1024
#define M_ (B_ * L_)      // 32768
#define K_ D_             // 1024

// GEMM tiling (HMMA warp-level)
#define BM 128
#define BN 64             // per-output (G and H each) N tile
#define BK 64
#define NKT (K_ / BK)     // 16
#define NTH 256

#define ROWB 144          // padded SMEM row stride bytes (128B data + 16B pad)
#define XT_BYTES (128 * ROWB)            // 18432 (one x tile)
#define WT_BYTES (64 * ROWB)             // 9216  (one W tile)
#define STAGE (2 * XT_BYTES + 4 * WT_BYTES)  // 73728
#define DYNSM (2 * STAGE)                // 147456

// stage-internal offsets
#define OXH 0
#define OXL (XT_BYTES)
#define OGH (2 * XT_BYTES)
#define OGL (2 * XT_BYTES + 1 * WT_BYTES)
#define OHH (2 * XT_BYTES + 2 * WT_BYTES)
#define OHL (2 * XT_BYTES + 3 * WT_BYTES)

// epilogue SMEM staging stride (floats)
#define EPS 68

// scan segmentation
#define NSEG 32
#define TSEG (L_ / NSEG)  // 128

// ---------------- device scratch (no allocs allowed) ----------------
__device__ __nv_bfloat16 g_xh[(size_t)M_ * K_];
__device__ __nv_bfloat16 g_xl[(size_t)M_ * K_];
__device__ __nv_bfloat16 g_wgh[(size_t)D_ * K_];
__device__ __nv_bfloat16 g_wgl[(size_t)D_ * K_];
__device__ __nv_bfloat16 g_whh[(size_t)D_ * K_];
__device__ __nv_bfloat16 g_whl[(size_t)D_ * K_];
__device__ float g_a[(size_t)M_ * D_];
__device__ float g_b[(size_t)M_ * D_];
__device__ float g_sA[B_ * NSEG * D_];
__device__ float g_sB[B_ * NSEG * D_];
__device__ float g_pA[B_ * NSEG * D_];
__device__ float g_pB[B_ * NSEG * D_];

// ---------------- helpers ----------------
__device__ __forceinline__ uint32_t smem_u32(const void* p) {
    uint32_t a;
    asm("{ .reg .u64 t; cvta.to.shared.u64 t, %1; cvt.u32.u64 %0, t; }" : "=r"(a) : "l"(p));
    return a;
}
__device__ __forceinline__ void cp16(uint32_t dst, const void* src) {
    asm volatile("cp.async.cg.shared.global [%0], [%1], 16;" :: "r"(dst), "l"(src));
}
__device__ __forceinline__ void ldsm4(uint32_t* r, uint32_t addr) {
    asm volatile("ldmatrix.sync.aligned.m8n8.x4.shared.b16 {%0,%1,%2,%3}, [%4];"
                 : "=r"(r[0]), "=r"(r[1]), "=r"(r[2]), "=r"(r[3]) : "r"(addr));
}
__device__ __forceinline__ void mma_bf16(float* d, const uint32_t* a, const uint32_t* b) {
    asm volatile("mma.sync.aligned.m16n8k16.row.col.f32.bf16.bf16.f32 "
                 "{%0,%1,%2,%3}, {%4,%5,%6,%7}, {%8,%9}, {%0,%1,%2,%3};"
                 : "+f"(d[0]), "+f"(d[1]), "+f"(d[2]), "+f"(d[3])
                 : "r"(a[0]), "r"(a[1]), "r"(a[2]), "r"(a[3]), "r"(b[0]), "r"(b[1]));
}

// ---------------------------------------------------------------------------
// Split fp32 -> bf16 hi/lo. tag: 0=x, 1=Wg, 2=Wh
// ---------------------------------------------------------------------------
__global__ void split_kernel(const float* __restrict__ src, int tag, int n4)
{
    int i = blockIdx.x * blockDim.x + threadIdx.x;
    if (i >= n4) return;
    __nv_bfloat16* hi;
    __nv_bfloat16* lo;
    if (tag == 0)      { hi = g_xh;  lo = g_xl;  }
    else if (tag == 1) { hi = g_wgh; lo = g_wgl; }
    else               { hi = g_whh; lo = g_whl; }

    float4 v = ((const float4*)src)[i];
    float f[4] = {v.x, v.y, v.z, v.w};
    __nv_bfloat16 h[4], l[4];
#pragma unroll
    for (int j = 0; j < 4; ++j) {
        __nv_bfloat16 hb = __float2bfloat16(f[j]);
        h[j] = hb;
        l[j] = __float2bfloat16(f[j] - __bfloat162float(hb));
    }
    ((uint2*)hi)[i] = *(uint2*)h;
    ((uint2*)lo)[i] = *(uint2*)l;
}

// ---------------------------------------------------------------------------
// HMMA dual GEMM + activations (3-term bf16 split, fp32 accum)
//   Dg = x @ Wg^T ; Dh = x @ Wh^T
//   a = sigmoid(Dg + bg) ; b = (1-a) * tanh(Dh + bh)
// ---------------------------------------------------------------------------
__global__ void __launch_bounds__(NTH, 1)
gemm_mma(const float* __restrict__ bg, const float* __restrict__ bh)
{
    extern __shared__ char smem[];
    __shared__ float s_bg[BN], s_bh[BN];

    const int tid   = threadIdx.x;
    const int wid   = tid >> 5;
    const int lane  = tid & 31;
    const int warpM = wid & 3;         // 0..3 -> m rows 32*warpM
    const int warpN = wid >> 2;        // 0..1 -> n cols 32*warpN
    const int m0 = blockIdx.y * BM;
    const int n0 = blockIdx.x * BN;

    if (tid < BN)            s_bg[tid]      = bg[n0 + tid];
    else if (tid < 2 * BN)   s_bh[tid - BN] = bh[n0 + tid - BN];

    const uint32_t sbase = smem_u32(smem);

    // ldmatrix per-lane offsets
    const int mat = lane >> 3;
    const int lr  = lane & 7;
    // A x4: mats = (m0-7,k0-7),(m8-15,k0-7),(m0-7,k8-15),(m8-15,k8-15)
    const uint32_t aoff = (uint32_t)((warpM * 32 + (mat & 1) * 8 + lr) * ROWB + (mat >> 1) * 16);
    // B x4: mats = (n0-7,k0-7),(n0-7,k8-15),(n8-15,k0-7),(n8-15,k8-15)
    const uint32_t boff = (uint32_t)((warpN * 32 + (mat >> 1) * 8 + lr) * ROWB + (mat & 1) * 16);

    float accG[2][4][4], accH[2][4][4];
#pragma unroll
    for (int h = 0; h < 2; ++h)
#pragma unroll
        for (int nb = 0; nb < 4; ++nb)
#pragma unroll
            for (int r = 0; r < 4; ++r) { accG[h][nb][r] = 0.f; accH[h][nb][r] = 0.f; }

    auto load_stage = [&](int kt, int buf) {
        const uint32_t sb = sbase + buf * STAGE;
        const int k0 = kt * BK;
#pragma unroll
        for (int i = 0; i < 4; ++i) {
            const int id = i * NTH + tid;           // 0..1023
            const int row = id >> 3, c = id & 7;
            const size_t so = (size_t)(m0 + row) * K_ + k0 + c * 8;
            const uint32_t doff = (uint32_t)(row * ROWB + c * 16);
            cp16(sb + OXH + doff, g_xh + so);
            cp16(sb + OXL + doff, g_xl + so);
        }
#pragma unroll
        for (int i = 0; i < 2; ++i) {
            const int id = i * NTH + tid;           // 0..511
            const int row = id >> 3, c = id & 7;
            const size_t so = (size_t)(n0 + row) * K_ + k0 + c * 8;
            const uint32_t doff = (uint32_t)(row * ROWB + c * 16);
            cp16(sb + OGH + doff, g_wgh + so);
            cp16(sb + OGL + doff, g_wgl + so);
            cp16(sb + OHH + doff, g_whh + so);
            cp16(sb + OHL + doff, g_whl + so);
        }
        asm volatile("cp.async.commit_group;" ::: "memory");
    };

    load_stage(0, 0);

#pragma unroll 1
    for (int kt = 0; kt < NKT; ++kt) {
        const int buf = kt & 1;
        if (kt + 1 < NKT) {
            load_stage(kt + 1, buf ^ 1);
            asm volatile("cp.async.wait_group 1;" ::: "memory");
        } else {
            asm volatile("cp.async.wait_group 0;" ::: "memory");
        }
        __syncthreads();

        const uint32_t sb = sbase + buf * STAGE;
#pragma unroll
        for (int kk = 0; kk < 4; ++kk) {
            const uint32_t kb = kk * 32;
            uint32_t Ah[2][4], Al[2][4];
#pragma unroll
            for (int h = 0; h < 2; ++h) {
                ldsm4(Ah[h], sb + OXH + aoff + h * 16 * ROWB + kb);
                ldsm4(Al[h], sb + OXL + aoff + h * 16 * ROWB + kb);
            }
            uint32_t Gh[4][2], Gl[4][2], Hh[4][2], Hl[4][2];
#pragma unroll
            for (int q = 0; q < 2; ++q) {
                const uint32_t bq = boff + q * 16 * ROWB + kb;
                uint32_t t[4];
                ldsm4(t, sb + OGH + bq);
                Gh[2*q][0]=t[0]; Gh[2*q][1]=t[1]; Gh[2*q+1][0]=t[2]; Gh[2*q+1][1]=t[3];
                ldsm4(t, sb + OGL + bq);
                Gl[2*q][0]=t[0]; Gl[2*q][1]=t[1]; Gl[2*q+1][0]=t[2]; Gl[2*q+1][1]=t[3];
                ldsm4(t, sb + OHH + bq);
                Hh[2*q][0]=t[0]; Hh[2*q][1]=t[1]; Hh[2*q+1][0]=t[2]; Hh[2*q+1][1]=t[3];
                ldsm4(t, sb + OHL + bq);
                Hl[2*q][0]=t[0]; Hl[2*q][1]=t[1]; Hl[2*q+1][0]=t[2]; Hl[2*q+1][1]=t[3];
            }
#pragma unroll
            for (int h = 0; h < 2; ++h)
#pragma unroll
                for (int nb = 0; nb < 4; ++nb) {
                    mma_bf16(accG[h][nb], Ah[h], Gh[nb]);
                    mma_bf16(accG[h][nb], Ah[h], Gl[nb]);
                    mma_bf16(accG[h][nb], Al[h], Gh[nb]);
                    mma_bf16(accH[h][nb], Ah[h], Hh[nb]);
                    mma_bf16(accH[h][nb], Ah[h], Hl[nb]);
                    mma_bf16(accH[h][nb], Al[h], Hh[nb]);
                }
        }
        __syncthreads();
    }

    // ---------------- epilogue: activations + coalesced stores ----------------
    float* sa  = (float*)smem;                       // 128 x EPS fp32
    float* sbf = (float*)(smem + 128 * EPS * 4);     // 128 x EPS fp32

#pragma unroll
    for (int h = 0; h < 2; ++h)
#pragma unroll
        for (int nb = 0; nb < 4; ++nb) {
            const int r0  = warpM * 32 + h * 16 + (lane >> 2);
            const int col = warpN * 32 + nb * 8 + 2 * (lane & 3);
            const float bg0 = s_bg[col], bg1 = s_bg[col + 1];
            const float bh0 = s_bh[col], bh1 = s_bh[col + 1];
#pragma unroll
            for (int p = 0; p < 2; ++p) {            // p=0: row r0, p=1: row r0+8
                const int row = r0 + p * 8;
                const float G0 = accG[h][nb][2*p + 0] + bg0;
                const float G1 = accG[h][nb][2*p + 1] + bg1;
                const float H0 = accH[h][nb][2*p + 0] + bh0;
                const float H1 = accH[h][nb][2*p + 1] + bh1;
                const float a0 = __fdividef(1.0f, 1.0f + __expf(-G0));
                const float a1 = __fdividef(1.0f, 1.0f + __expf(-G1));
                const float c0 = __fdividef(2.0f, 1.0f + __expf(-2.0f * H0)) - 1.0f;
                const float c1 = __fdividef(2.0f, 1.0f + __expf(-2.0f * H1)) - 1.0f;
                float2 av = make_float2(a0, a1);
                float2 bv = make_float2((1.0f - a0) * c0, (1.0f - a1) * c1);
                *(float2*)(sa  + row * EPS + col) = av;
                *(float2*)(sbf + row * EPS + col) = bv;
            }
        }
    __syncthreads();

#pragma unroll
    for (int i = 0; i < 8; ++i) {
        const int id = i * NTH + tid;                // 0..2047
        const int row = id >> 4, slot = id & 15;
        const size_t o = (size_t)(m0 + row) * D_ + n0 + slot * 4;
        *(float4*)(g_a + o) = *(float4*)(sa  + row * EPS + slot * 4);
        *(float4*)(g_b + o) = *(float4*)(sbf + row * EPS + slot * 4);
    }
}

// ---------------------------------------------------------------------------
// Scan pass 1: per-segment affine reduction
// ---------------------------------------------------------------------------
__global__ void scan_seg()
{
    const int d = blockIdx.x * blockDim.x + threadIdx.x;
    const int s = blockIdx.y;
    const int b = blockIdx.z;

    size_t base = ((size_t)(b * L_ + s * TSEG)) * D_ + d;
    float A = 1.f, Bv = 0.f;
#pragma unroll 8
    for (int t = 0; t < TSEG; ++t) {
        const float a  = g_a[base];
        const float bb = g_b[base];
        Bv = fmaf(a, Bv, bb);
        A  = A * a;
        base += D_;
    }
    const size_t o = ((size_t)(b * NSEG + s)) * D_ + d;
    g_sA[o] = A;
    g_sB[o] = Bv;
}

// ---------------------------------------------------------------------------
// Scan pass 2: exclusive prefix over segments
// ---------------------------------------------------------------------------
__global__ void scan_prefix()
{
    const int idx = blockIdx.x * blockDim.x + threadIdx.x;
    const int b = idx >> 10;
    const int d = idx & (D_ - 1);

    float PA = 1.f, PB = 0.f;
#pragma unroll
    for (int s = 0; s < NSEG; ++s) {
        const size_t o = ((size_t)(b * NSEG + s)) * D_ + d;
        g_pA[o] = PA;
        g_pB[o] = PB;
        const float A  = g_sA[o];
        const float Bs = g_sB[o];
        PB = fmaf(A, PB, Bs);
        PA = PA * A;
    }
}

// ---------------------------------------------------------------------------
// Scan pass 3: apply prefix, write h_t
// ---------------------------------------------------------------------------
__global__ void scan_apply(const float* __restrict__ hidden,
                           float* __restrict__ out)
{
    const int d = blockIdx.x * blockDim.x + threadIdx.x;
    const int s = blockIdx.y;
    const int b = blockIdx.z;

    const size_t po = ((size_t)(b * NSEG + s)) * D_ + d;
    float h = fmaf(g_pA[po], hidden[(size_t)b * D_ + d], g_pB[po]);

    size_t base = ((size_t)(b * L_ + s * TSEG)) * D_ + d;
#pragma unroll 8
    for (int t = 0; t < TSEG; ++t) {
        const float a  = g_a[base];
        const float bb = g_b[base];
        h = fmaf(a, h, bb);
        out[base] = h;
        base += D_;
    }
}

// ---------------------------------------------------------------------------
extern "C" void kernel_launch(void* const* d_in, const int* in_sizes, int n_in,
                              void* d_out, int out_size)
{
    const float* x      = (const float*)d_in[0];
    const float* hidden = (const float*)d_in[1];
    const float* Wg     = (const float*)d_in[2];
    const float* bg     = (const float*)d_in[3];
    const float* Wh     = (const float*)d_in[4];
    const float* bh     = (const float*)d_in[5];
    float* out = (float*)d_out;

    // bf16 hi/lo splits
    split_kernel<<<(M_ * K_ / 4) / 256, 256>>>(x,  0, M_ * K_ / 4);
    split_kernel<<<(D_ * K_ / 4) / 256, 256>>>(Wg, 1, D_ * K_ / 4);
    split_kernel<<<(D_ * K_ / 4) / 256, 256>>>(Wh, 2, D_ * K_ / 4);

    // tensor-core dual GEMM + activations
    cudaFuncSetAttribute(gemm_mma, cudaFuncAttributeMaxDynamicSharedMemorySize, DYNSM);
    dim3 gg(D_ / BN, M_ / BM);          // (16, 256)
    gemm_mma<<<gg, NTH, DYNSM>>>(bg, bh);

    // scan
    dim3 sg(D_ / 256, NSEG, B_);
    scan_seg<<<sg, 256>>>();
    scan_prefix<<<(B_ * D_) / 256, 256>>>();
    scan_apply<<<sg, 256>>>(hidden, out);
}